// round 15
// baseline (speedup 1.0000x reference)
#include <cuda_runtime.h>
#include <cuda_bf16.h>
#include <cuda_fp16.h>
#include <math.h>
#include <stdint.h>

#define H 256
#define FIN 58
#define K1P 64
#define N_MAX 100000
#define E_MAX 3200000

typedef __nv_bfloat16 bf16;

// ---------------- scratch (device globals; no allocation allowed) ------------
__device__ float  g_R  [(size_t)N_MAX * H];
__device__ float  g_Rn [(size_t)N_MAX * H];
__device__ float  g_Gn [(size_t)N_MAX * H];
__device__ bf16   g_Rh [(size_t)N_MAX * H];
__device__ bf16   g_Rl [(size_t)N_MAX * H];
__device__ __half g_Rf [(size_t)N_MAX * H];
__device__ bf16   g_RTh[(size_t)H * N_MAX];
__device__ bf16   g_RTl[(size_t)H * N_MAX];
__device__ bf16   g_xh [(size_t)N_MAX * K1P];
__device__ bf16   g_xl [(size_t)N_MAX * K1P];
__device__ bf16   g_W1Th[H * K1P];
__device__ bf16   g_W1Tl[H * K1P];
__device__ float  g_kv [H * H];                  // G = R^T R
__device__ float  g_Cqk[H * H];                  // Wq Wk^T (constant)
__device__ float  g_Mk [H * H];                  // Wk Wk^T (constant)
__device__ float  g_Mq [H * H];                  // Wq Wq^T (constant)
__device__ float  g_wc [H];                      // Wk . bq
__device__ float  g_wb [H];                      // Wq . bk
__device__ float  g_cc [1];                      // bq . bk
__device__ bf16   g_W2Th[H * H];
__device__ bf16   g_W2Tl[H * H];
__device__ float  g_ksum[H];
__device__ float  g_qsum[H];
__device__ float  g_u  [H];
__device__ float  g_c2 [H];
__device__ float  g_scal[4];                     // [k2, q2, s, c_den]
__device__ float  g_dinv[N_MAX];
__device__ float  g_denp[N_MAX];
__device__ float  g_stats[2 + 2 * H];            // vsum at [2+256..2+511]
// CSR structures
__device__ int    g_degi[N_MAX];
__device__ int    g_cur [N_MAX];
__device__ int    g_off [N_MAX + 1];
__device__ int    g_bsum[128];
__device__ int    g_esrc[E_MAX];
__device__ float  g_ew  [E_MAX];

// ---------------- PTX helpers --------------------------------------------------
__device__ __forceinline__ uint32_t smem_u32(const void* p) {
    uint32_t a;
    asm("{ .reg .u64 t; cvta.to.shared.u64 t, %1; cvt.u32.u64 %0, t; }" : "=r"(a) : "l"(p));
    return a;
}
__device__ __forceinline__ void ldsm4(uint32_t* r, uint32_t addr) {
    asm volatile("ldmatrix.sync.aligned.m8n8.x4.shared.b16 {%0,%1,%2,%3}, [%4];"
                 : "=r"(r[0]), "=r"(r[1]), "=r"(r[2]), "=r"(r[3]) : "r"(addr));
}
__device__ __forceinline__ void mma16816(float* c, const uint32_t* a, uint32_t b0, uint32_t b1) {
    asm volatile("mma.sync.aligned.m16n8k16.row.col.f32.bf16.bf16.f32 "
                 "{%0,%1,%2,%3}, {%4,%5,%6,%7}, {%8,%9}, {%0,%1,%2,%3};"
                 : "+f"(c[0]), "+f"(c[1]), "+f"(c[2]), "+f"(c[3])
                 : "r"(a[0]), "r"(a[1]), "r"(a[2]), "r"(a[3]), "r"(b0), "r"(b1));
}
__device__ __forceinline__ void cpa16(uint32_t dst, const void* src, bool pred) {
    int sz = pred ? 16 : 0;
    asm volatile("cp.async.cg.shared.global [%0], [%1], 16, %2;"
                 :: "r"(dst), "l"(src), "r"(sz));
}
#define CP_COMMIT() asm volatile("cp.async.commit_group;" ::: "memory")
#define SW128(o) ((o) ^ (((o) >> 3) & 0x70))

// ---------------- tiny utility kernels ---------------------------------------
__global__ void zero2_k() {
    int i = blockIdx.x * blockDim.x + threadIdx.x;
    if (i < H * H) g_kv[i] = 0.f;
    if (i < 2 + 2 * H) g_stats[i] = 0.f;
}
__global__ void mirror_G() {
    int i = blockIdx.x * blockDim.x + threadIdx.x;
    if (i >= 128 * 128) return;
    int r = 128 + (i >> 7), c = i & 127;
    g_kv[r * H + c] = g_kv[c * H + r];
}
__global__ void zero_i2(int n) {
    int i = blockIdx.x * blockDim.x + threadIdx.x;
    if (i < n) { g_degi[i] = 0; g_cur[i] = 0; }
}
__global__ void cnt_deg(const int* __restrict__ col, int E) {
    int i = blockIdx.x * blockDim.x + threadIdx.x;
    if (i < E) atomicAdd(&g_degi[col[i]], 1);
}
__global__ void invsqrt_k(int n) {
    int i = blockIdx.x * blockDim.x + threadIdx.x;
    if (i < n) {
        int d = g_degi[i];
        g_dinv[i] = (d > 0) ? rsqrtf((float)d) : 0.f;
    }
}
__global__ __launch_bounds__(256) void scan1(int n) {
    __shared__ int s[256];
    int b = blockIdx.x, t = threadIdx.x;
    int base = b * 1024 + t * 4;
    int v0 = 0, v1 = 0, v2 = 0, v3 = 0;
    if (base + 0 < n) v0 = g_degi[base + 0];
    if (base + 1 < n) v1 = g_degi[base + 1];
    if (base + 2 < n) v2 = g_degi[base + 2];
    if (base + 3 < n) v3 = g_degi[base + 3];
    int tsum = v0 + v1 + v2 + v3;
    s[t] = tsum;
    __syncthreads();
    for (int o = 1; o < 256; o <<= 1) {
        int x = 0;
        if (t >= o) x = s[t - o];
        __syncthreads();
        s[t] += x;
        __syncthreads();
    }
    int ex = s[t] - tsum;
    if (base + 0 < n) g_off[base + 0] = ex;
    if (base + 1 < n) g_off[base + 1] = ex + v0;
    if (base + 2 < n) g_off[base + 2] = ex + v0 + v1;
    if (base + 3 < n) g_off[base + 3] = ex + v0 + v1 + v2;
    if (t == 255) g_bsum[b] = s[255];
}
__global__ void scan2(int nb) {
    __shared__ int s[128];
    int t = threadIdx.x;
    int v = (t < nb) ? g_bsum[t] : 0;
    s[t] = v;
    __syncthreads();
    for (int o = 1; o < 128; o <<= 1) {
        int x = 0;
        if (t >= o) x = s[t - o];
        __syncthreads();
        s[t] += x;
        __syncthreads();
    }
    g_bsum[t] = s[t] - v;
}
__global__ void scan3(int n, int E) {
    int i = blockIdx.x * blockDim.x + threadIdx.x;
    if (i < n) g_off[i] += g_bsum[i >> 10];
    if (i == 0) g_off[n] = E;
}
__global__ void edge_scatter(const int* __restrict__ erow, const int* __restrict__ ecol, int E) {
    int e = blockIdx.x * blockDim.x + threadIdx.x;
    if (e >= E) return;
    int c = ecol[e], r = erow[e];
    int pos = g_off[c] + atomicAdd(&g_cur[c], 1);
    g_esrc[pos] = r;
    g_ew[pos] = g_dinv[r] * g_dinv[c];
}

__device__ __forceinline__ void split_store(float v, bf16* ph, bf16* pl, size_t idx) {
    bf16 h = __float2bfloat16(v);
    ph[idx] = h;
    pl[idx] = __float2bfloat16(v - __bfloat162float(h));
}
__global__ void build_xplanes(const float* __restrict__ x, int n) {
    int idx = blockIdx.x * blockDim.x + threadIdx.x;
    if (idx >= n * K1P) return;
    int r = idx >> 6, c = idx & 63;
    float v = (c < FIN) ? x[(size_t)r * FIN + c] : 0.f;
    split_store(v, g_xh, g_xl, idx);
}
__global__ void build_w1T(const float* __restrict__ W1) {
    int idx = blockIdx.x * blockDim.x + threadIdx.x;
    if (idx >= H * K1P) return;
    int nn = idx >> 6, k = idx & 63;
    float v = (k < FIN) ? W1[k * H + nn] : 0.f;
    split_store(v, g_W1Th, g_W1Tl, idx);
}
// constants (prologue, stream C): row a of Mk, Mq, Cqk; wc, wb, cc
__global__ __launch_bounds__(256) void build_const(
    const float* __restrict__ Wk, const float* __restrict__ Wq,
    const float* __restrict__ bk, const float* __restrict__ bq)
{
    int a = blockIdx.x;
    int w = threadIdx.x >> 5, l = threadIdx.x & 31;
    __shared__ float rk[256], rq[256];
    rk[threadIdx.x] = Wk[a * 256 + threadIdx.x];
    rq[threadIdx.x] = Wq[a * 256 + threadIdx.x];
    __syncthreads();
    for (int b = w; b < 256; b += 8) {
        float pk = 0.f, pq = 0.f, pc = 0.f;
        for (int n = l; n < 256; n += 32) {
            float wkb = Wk[b * 256 + n];
            pk += rk[n] * wkb;
            pq += rq[n] * Wq[b * 256 + n];
            pc += rq[n] * wkb;          // Cqk[a][b] = Wq[a,:].Wk[b,:]
        }
        #pragma unroll
        for (int o = 16; o > 0; o >>= 1) {
            pk += __shfl_xor_sync(0xffffffffu, pk, o);
            pq += __shfl_xor_sync(0xffffffffu, pq, o);
            pc += __shfl_xor_sync(0xffffffffu, pc, o);
        }
        if (l == 0) {
            g_Mk [a * 256 + b] = pk;
            g_Mq [a * 256 + b] = pq;
            g_Cqk[a * 256 + b] = pc;
        }
    }
    if (w == 0) {
        float p = 0.f, p2 = 0.f;
        for (int n = l; n < 256; n += 32) {
            p  += rk[n] * bq[n];
            p2 += rq[n] * bk[n];
        }
        #pragma unroll
        for (int o = 16; o > 0; o >>= 1) {
            p  += __shfl_xor_sync(0xffffffffu, p, o);
            p2 += __shfl_xor_sync(0xffffffffu, p2, o);
        }
        if (l == 0) { g_wc[a] = p; g_wb[a] = p2; }
    }
    if (a == 0 && w == 1) {
        float p = 0.f;
        for (int n = l; n < 256; n += 32) p += bq[n] * bk[n];
        #pragma unroll
        for (int o = 16; o > 0; o >>= 1) p += __shfl_xor_sync(0xffffffffu, p, o);
        if (l == 0) g_cc[0] = p;
    }
}
// merged hi+lo tiled transpose (once per call, iteration-0 R^T)
__global__ void transpose2_bf16(const bf16* __restrict__ ih, const bf16* __restrict__ il,
                                bf16* __restrict__ oh, bf16* __restrict__ ol,
                                int rows, int istride, int ostride) {
    __shared__ bf16 th[32][33], tl[32][33];
    int r0 = blockIdx.x * 32, c0 = blockIdx.y * 32;
    for (int i = threadIdx.y; i < 32; i += 8) {
        int r = r0 + i, c = c0 + threadIdx.x;
        bf16 zh = __float2bfloat16(0.f);
        th[i][threadIdx.x] = (r < rows) ? ih[(size_t)r * istride + c] : zh;
        tl[i][threadIdx.x] = (r < rows) ? il[(size_t)r * istride + c] : zh;
    }
    __syncthreads();
    for (int i = threadIdx.y; i < 32; i += 8) {
        int oc = r0 + threadIdx.x, orow = c0 + i;
        if (oc < rows) {
            oh[(size_t)orow * ostride + oc] = th[threadIdx.x][i];
            ol[(size_t)orow * ostride + oc] = tl[threadIdx.x][i];
        }
    }
}

// ---------------- mma.sync split-bf16 GEMM, 2-stage cp.async pipeline ---------
// EPI 1: attn  v = ((acc + c2[c])*s + vsum[c]) / (s*denp[r] + fN)
// EPI 2: atomic fp32 into g_kv; gsym=1 remaps 6 blocks to the symmetric set.
// EPI 3: input GEMM: relu(acc + b1[c]) -> R, Rh, Rl, Rf
#define STAGE_BYTES 49152
template <int EPI>
__global__ __launch_bounds__(256, 2) void mma_gemm(
    const bf16* __restrict__ Ah_, const bf16* __restrict__ Al_, int lda,
    const bf16* __restrict__ Bh_, const bf16* __restrict__ Bl_, int ldb,
    int Mrows, int Ktot, int kchunk,
    const float* __restrict__ e0,
    float* __restrict__ outf, int gsym, float fN)
{
    extern __shared__ char smem[];
    const int tid = threadIdx.x, wid = tid >> 5, lane = tid & 31;
    const int wm = (wid & 3) * 32;
    const int wn = (wid >> 2) * 32;
    int bx = blockIdx.x, by = blockIdx.y;
    if (gsym) {
        if (bx >= 4) { by = 1; bx = bx - 2; } else { by = 0; }
    }
    const int row0 = by * 128;
    const int ncol0 = bx * 64;
    const int k0 = blockIdx.z * kchunk;
    int kend = k0 + kchunk; if (kend > Ktot) kend = Ktot;
    const uint32_t sbase = smem_u32(smem);

    auto fill = [&](int stage, int ks) {
        uint32_t sa = sbase + stage * STAGE_BYTES;
        #pragma unroll
        for (int it = 0; it < 4; it++) {
            int ch = tid + it * 256;
            int r = ch >> 3, c8 = ch & 7;
            int g = row0 + r;
            int kb = ks + c8 * 8;
            uint32_t off = SW128((uint32_t)(r * 128 + c8 * 16));
            bool p = (g < Mrows) && (kb + 8 <= kend);
            const bf16* ph = p ? &Ah_[(size_t)g * lda + kb] : Ah_;
            const bf16* pl = p ? &Al_[(size_t)g * lda + kb] : Al_;
            cpa16(sa + off, ph, p);
            cpa16(sa + 16384 + off, pl, p);
        }
        #pragma unroll
        for (int it = 0; it < 2; it++) {
            int ch = tid + it * 256;
            int r = ch >> 3, c8 = ch & 7;
            int gn = ncol0 + r;
            int kb = ks + c8 * 8;
            uint32_t off = SW128((uint32_t)(r * 128 + c8 * 16));
            bool p = (kb + 8 <= kend);
            const bf16* ph = p ? &Bh_[(size_t)gn * ldb + kb] : Bh_;
            const bf16* pl = p ? &Bl_[(size_t)gn * ldb + kb] : Bl_;
            cpa16(sa + 32768 + off, ph, p);
            cpa16(sa + 40960 + off, pl, p);
        }
    };

    float acc[2][4][4] = {};
    int stage = 0;
    fill(0, k0);
    CP_COMMIT();

    for (int ks = k0; ks < kend; ks += 64) {
        int nxt = ks + 64;
        if (nxt < kend) {
            fill(stage ^ 1, nxt);
            CP_COMMIT();
            asm volatile("cp.async.wait_group 1;" ::: "memory");
        } else {
            asm volatile("cp.async.wait_group 0;" ::: "memory");
        }
        __syncthreads();

        uint32_t base = sbase + stage * STAGE_BYTES;
        #pragma unroll
        for (int kc = 0; kc < 4; kc++) {
            uint32_t ah[2][4], al[2][4], bh[2][4], bl[2][4];
            #pragma unroll
            for (int mt = 0; mt < 2; mt++) {
                uint32_t off = SW128((uint32_t)((wm + mt * 16 + (lane & 15)) * 128 +
                                                (kc * 16 + (lane >> 4) * 8) * 2));
                ldsm4(ah[mt], base + off);
                ldsm4(al[mt], base + 16384 + off);
            }
            #pragma unroll
            for (int ntp = 0; ntp < 2; ntp++) {
                uint32_t off = SW128((uint32_t)((wn + ntp * 16 + ((lane >> 4) & 1) * 8 + (lane & 7)) * 128 +
                                                (kc * 16 + ((lane >> 3) & 1) * 8) * 2));
                ldsm4(bh[ntp], base + 32768 + off);
                ldsm4(bl[ntp], base + 40960 + off);
            }
            #pragma unroll
            for (int mt = 0; mt < 2; mt++)
                #pragma unroll
                for (int nt = 0; nt < 4; nt++) {
                    uint32_t b0h = bh[nt >> 1][(nt & 1) * 2], b1h = bh[nt >> 1][(nt & 1) * 2 + 1];
                    uint32_t b0l = bl[nt >> 1][(nt & 1) * 2], b1l = bl[nt >> 1][(nt & 1) * 2 + 1];
                    mma16816(acc[mt][nt], ah[mt], b0h, b1h);
                    mma16816(acc[mt][nt], ah[mt], b0l, b1l);
                    mma16816(acc[mt][nt], al[mt], b0h, b1h);
                }
        }
        __syncthreads();
        stage ^= 1;
    }

    if (EPI == 1) {
        float s_val = g_scal[2];
        #pragma unroll
        for (int mt = 0; mt < 2; mt++)
            #pragma unroll
            for (int rg = 0; rg < 4; rg++) {
                int r = row0 + wm + mt * 16 + (lane >> 2) + ((rg >> 1) & 1) * 8;
                if (r >= Mrows) continue;
                float id = 1.0f / (s_val * g_denp[r] + fN);
                #pragma unroll
                for (int nt = 0; nt < 4; nt++) {
                    int c = ncol0 + wn + nt * 8 + (lane & 3) * 2 + (rg & 1);
                    float v = ((acc[mt][nt][rg] + e0[c]) * s_val + g_stats[2 + H + c]) * id;
                    outf[(size_t)r * H + c] = v;
                }
            }
    } else if (EPI == 3) {
        #pragma unroll
        for (int mt = 0; mt < 2; mt++)
            #pragma unroll
            for (int rg = 0; rg < 4; rg++) {
                int r = row0 + wm + mt * 16 + (lane >> 2) + ((rg >> 1) & 1) * 8;
                if (r >= Mrows) continue;
                #pragma unroll
                for (int nt = 0; nt < 4; nt++) {
                    int c = ncol0 + wn + nt * 8 + (lane & 3) * 2 + (rg & 1);
                    float v = fmaxf(acc[mt][nt][rg] + e0[c], 0.f);
                    size_t idx = (size_t)r * H + c;
                    g_R[idx] = v;
                    split_store(v, g_Rh, g_Rl, idx);
                    g_Rf[idx] = __float2half(v);
                }
            }
    } else {
        #pragma unroll
        for (int mt = 0; mt < 2; mt++)
            #pragma unroll
            for (int rg = 0; rg < 4; rg++) {
                int r = row0 + wm + mt * 16 + (lane >> 2) + ((rg >> 1) & 1) * 8;
                if (r >= Mrows) continue;
                #pragma unroll
                for (int nt = 0; nt < 4; nt++) {
                    int c = ncol0 + wn + nt * 8 + (lane & 3) * 2 + (rg & 1);
                    atomicAdd(&g_kv[(size_t)r * H + c], acc[mt][nt][rg]);
                }
            }
    }
}

// ---------------- vsum: colsum of R ------------------------------------------
__global__ __launch_bounds__(256) void vsum_k(int M) {
    int t = threadIdx.x;
    int r0 = blockIdx.x * 128;
    int rend = r0 + 128; if (rend > M) rend = M;
    float vs = 0.f;
    for (int r = r0; r < rend; r++) vs += g_R[(size_t)r * 256 + t];
    atomicAdd(&g_stats[2 + 256 + t], vs);
}

// ---- pre_den: ksum, qsum, u, c_den — needs ONLY vsum -------------------------
__global__ __launch_bounds__(256) void pre_den(
    const float* __restrict__ Wk, const float* __restrict__ Wq,
    const float* __restrict__ bk, const float* __restrict__ bq, float fN)
{
    __shared__ float sks[256];
    int t = threadIdx.x;
    float ks = 0.f, qs = 0.f;
    for (int i = 0; i < 256; i++) {
        float v = g_stats[2 + 256 + i];
        ks += v * Wk[i * 256 + t];
        qs += v * Wq[i * 256 + t];
    }
    ks += fN * bk[t];
    qs += fN * bq[t];
    g_ksum[t] = ks;
    g_qsum[t] = qs;
    sks[t] = ks;
    __syncthreads();
    float u = 0.f;
    for (int m = 0; m < 256; m++) u += Wq[t * 256 + m] * sks[m];
    g_u[t] = u;
    __shared__ float red[256];
    red[t] = bq[t] * sks[t];
    __syncthreads();
    for (int o = 128; o > 0; o >>= 1) {
        if (t < o) red[t] += red[t + o];
        __syncthreads();
    }
    if (t == 0) g_scal[3] = red[0];
}

// denp_n = R_n . u + c_den
__global__ void den_p(int M) {
    int gw = (blockIdx.x * blockDim.x + threadIdx.x) >> 5;
    int l = threadIdx.x & 31;
    if (gw >= M) return;
    size_t base = (size_t)gw * 256;
    float sum = 0.f;
    #pragma unroll
    for (int j = 0; j < 8; j++) {
        int idx = j * 32 + l;
        sum += g_R[base + idx] * g_u[idx];
    }
    #pragma unroll
    for (int o = 16; o > 0; o >>= 1) sum += __shfl_xor_sync(0xffffffffu, sum, o);
    if (l == 0) g_denp[gw] = sum + g_scal[3];
}

// W2 = Cqk @ G + wb (x) vsum; write W2^T split planes directly
__global__ __launch_bounds__(256) void small_w2() {
    const int i0 = blockIdx.y * 64, d0 = blockIdx.x * 64;
    __shared__ float sA[8][64], sB[8][64];
    const int tid = threadIdx.x;
    const int tr = tid >> 4, tc = tid & 15;
    float acc[4][4] = {};
    for (int k0 = 0; k0 < 256; k0 += 8) {
        #pragma unroll
        for (int t = tid; t < 512; t += 256) {
            int ii = t >> 3, kk = t & 7;
            sA[kk][ii] = g_Cqk[(i0 + ii) * 256 + k0 + kk];
        }
        #pragma unroll
        for (int t = tid; t < 512; t += 256) {
            int kk = t >> 6, d = t & 63;
            sB[kk][d] = g_kv[(k0 + kk) * 256 + d0 + d];
        }
        __syncthreads();
        #pragma unroll
        for (int kk = 0; kk < 8; kk++) {
            float a[4], bb[4];
            #pragma unroll
            for (int i = 0; i < 4; i++) a[i] = sA[kk][tr * 4 + i];
            #pragma unroll
            for (int j = 0; j < 4; j++) bb[j] = sB[kk][tc * 4 + j];
            #pragma unroll
            for (int i = 0; i < 4; i++)
                #pragma unroll
                for (int j = 0; j < 4; j++)
                    acc[i][j] += a[i] * bb[j];
        }
        __syncthreads();
    }
    #pragma unroll
    for (int i = 0; i < 4; i++) {
        int ii = i0 + tr * 4 + i;
        float wbv = g_wb[ii];
        #pragma unroll
        for (int j = 0; j < 4; j++) {
            int d = d0 + tc * 4 + j;
            float v = acc[i][j] + wbv * g_stats[2 + 256 + d];
            split_store(v, g_W2Th, g_W2Tl, (size_t)d * 256 + ii);
        }
    }
}

// stats: k2 = <G,Mk> + 2 ksum.bk - N|bk|^2 ; q2 likewise; s; c2 = wc^T G[:,d] + cc*vsum[d]
__global__ __launch_bounds__(256) void stats2(
    const float* __restrict__ bk, const float* __restrict__ bq, float fN)
{
    int t = threadIdx.x;
    float pk = 0.f, pq = 0.f;
    for (int j = 0; j < 256; j++) {
        float g = g_kv[t * 256 + j];
        pk += g * g_Mk[t * 256 + j];
        pq += g * g_Mq[t * 256 + j];
    }
    pk += 2.f * bk[t] * g_ksum[t] - fN * bk[t] * bk[t];
    pq += 2.f * bq[t] * g_qsum[t] - fN * bq[t] * bq[t];
    __shared__ float rk[256], rq[256];
    rk[t] = pk; rq[t] = pq;
    __syncthreads();
    for (int o = 128; o > 0; o >>= 1) {
        if (t < o) { rk[t] += rk[t + o]; rq[t] += rq[t + o]; }
        __syncthreads();
    }
    if (t == 0) {
        g_scal[0] = rk[0];
        g_scal[1] = rq[0];
        g_scal[2] = rsqrtf(rk[0]) * rsqrtf(rq[0]);
    }
    float c = 0.f;
    for (int a = 0; a < 256; a++) c += g_wc[a] * g_kv[a * 256 + t];
    g_c2[t] = c + g_cc[0] * g_stats[2 + 256 + t];
}

// ---------------- GCN gather (fp16 plane, 256-dim, writes Gn, unroll 4) -------
__global__ __launch_bounds__(256) void gcn_gather_f16(int Nn) {
    int warp = (blockIdx.x * blockDim.x + threadIdx.x) >> 5;
    if (warp >= Nn) return;
    int l = threadIdx.x & 31;
    int beg = g_off[warp], end = g_off[warp + 1];
    float a[8] = {};
    const int4* Rb = (const int4*)g_Rf;
    int e = beg;
    for (; e + 4 <= end; e += 4) {
        int s0 = __ldg(&g_esrc[e]);
        int s1 = __ldg(&g_esrc[e + 1]);
        int s2 = __ldg(&g_esrc[e + 2]);
        int s3 = __ldg(&g_esrc[e + 3]);
        float w0 = __ldg(&g_ew[e]);
        float w1 = __ldg(&g_ew[e + 1]);
        float w2 = __ldg(&g_ew[e + 2]);
        float w3 = __ldg(&g_ew[e + 3]);
        int4 p0 = __ldg(&Rb[(size_t)s0 * 32 + l]);
        int4 p1 = __ldg(&Rb[(size_t)s1 * 32 + l]);
        int4 p2 = __ldg(&Rb[(size_t)s2 * 32 + l]);
        int4 p3 = __ldg(&Rb[(size_t)s3 * 32 + l]);
        const __half2* h0 = (const __half2*)&p0;
        const __half2* h1 = (const __half2*)&p1;
        const __half2* h2 = (const __half2*)&p2;
        const __half2* h3 = (const __half2*)&p3;
        #pragma unroll
        for (int j = 0; j < 4; j++) {
            float2 v0 = __half22float2(h0[j]);
            float2 v1 = __half22float2(h1[j]);
            float2 v2 = __half22float2(h2[j]);
            float2 v3 = __half22float2(h3[j]);
            a[2 * j]     += w0 * v0.x + w1 * v1.x + w2 * v2.x + w3 * v3.x;
            a[2 * j + 1] += w0 * v0.y + w1 * v1.y + w2 * v2.y + w3 * v3.y;
        }
    }
    for (; e < end; e++) {
        int s0 = __ldg(&g_esrc[e]);
        float w0 = __ldg(&g_ew[e]);
        int4 p0 = __ldg(&Rb[(size_t)s0 * 32 + l]);
        const __half2* h0 = (const __half2*)&p0;
        #pragma unroll
        for (int j = 0; j < 4; j++) {
            float2 v0 = __half22float2(h0[j]);
            a[2 * j]     += w0 * v0.x;
            a[2 * j + 1] += w0 * v0.y;
        }
    }
    float* dst = &g_Gn[(size_t)warp * 256 + l * 8];
    *(float4*)&dst[0] = *(float4*)&a[0];
    *(float4*)&dst[4] = *(float4*)&a[4];
}

// ---------------- blend + LayerNorm + RT planes + readout ---------------------
__global__ __launch_bounds__(256) void blend_ln(
    const float* __restrict__ alpha_p,
    const float* __restrict__ gamma, const float* __restrict__ beta,
    const float* __restrict__ Wr, const float* __restrict__ br,
    const float* __restrict__ wgt, int sidx,
    float* __restrict__ out, int M, int writeRT)
{
    __shared__ bf16 sh[32][260];
    __shared__ bf16 sl[32][260];
    const int n0 = blockIdx.x * 32;
    const int wid = threadIdx.x >> 5, l = threadIdx.x & 31;
    const float al = alpha_p[0];
    const float* wr = Wr + sidx * 256;

    #pragma unroll
    for (int i = 0; i < 4; i++) {
        int nl = wid * 4 + i;
        int node = n0 + nl;
        if (node < M) {
            size_t base = (size_t)node * 256;
            float h[8]; float sum = 0.f, sq = 0.f;
            #pragma unroll
            for (int j = 0; j < 8; j++) {
                int idx = j * 32 + l;
                float v = al * (g_Rn[base + idx] + g_Gn[base + idx]) + (1.f - al) * g_R[base + idx];
                h[j] = v; sum += v; sq += v * v;
            }
            #pragma unroll
            for (int o = 16; o > 0; o >>= 1) {
                sum += __shfl_xor_sync(0xffffffffu, sum, o);
                sq  += __shfl_xor_sync(0xffffffffu, sq, o);
            }
            float mu  = sum * (1.f / 256.f);
            float var = sq * (1.f / 256.f) - mu * mu;
            float rstd = rsqrtf(var + 1e-5f);
            float dot = 0.f;
            #pragma unroll
            for (int j = 0; j < 8; j++) {
                int idx = j * 32 + l;
                float y = (h[j] - mu) * rstd * gamma[idx] + beta[idx];
                g_R[base + idx] = y;
                bf16 yh = __float2bfloat16(y);
                bf16 yl = __float2bfloat16(y - __bfloat162float(yh));
                g_Rh[base + idx] = yh;
                g_Rl[base + idx] = yl;
                g_Rf[base + idx] = __float2half(y);
                sh[nl][idx] = yh;
                sl[nl][idx] = yl;
                dot += y * wr[idx];
            }
            #pragma unroll
            for (int o = 16; o > 0; o >>= 1) dot += __shfl_xor_sync(0xffffffffu, dot, o);
            if (l == 0) out[node] += wgt[sidx] * (dot + br[sidx]);
        }
    }

    if (writeRT) {
        __syncthreads();
        int d = threadIdx.x;
        size_t Nn = (size_t)M;
        if (n0 + 32 <= M && ((Nn * 2) & 15) == 0) {
            uint32_t ph[16], pl[16];
            #pragma unroll
            for (int p = 0; p < 16; p++) {
                uint32_t h0 = __bfloat16_as_ushort(sh[p * 2][d]);
                uint32_t h1 = __bfloat16_as_ushort(sh[p * 2 + 1][d]);
                uint32_t l0 = __bfloat16_as_ushort(sl[p * 2][d]);
                uint32_t l1 = __bfloat16_as_ushort(sl[p * 2 + 1][d]);
                ph[p] = h0 | (h1 << 16);
                pl[p] = l0 | (l1 << 16);
            }
            size_t gb = (size_t)d * Nn + n0;
            #pragma unroll
            for (int q = 0; q < 4; q++) {
                *(int4*)&g_RTh[gb + q * 8] = *(int4*)&ph[q * 4];
                *(int4*)&g_RTl[gb + q * 8] = *(int4*)&pl[q * 4];
            }
        } else {
            for (int nl = 0; nl < 32; nl++) {
                if (n0 + nl < M) {
                    g_RTh[(size_t)d * Nn + n0 + nl] = sh[nl][d];
                    g_RTl[(size_t)d * Nn + n0 + nl] = sl[nl][d];
                }
            }
        }
    }
}

__global__ void readout0(const float* __restrict__ Wr, const float* __restrict__ br,
                         const float* __restrict__ wgt, float* __restrict__ out, int M)
{
    int gw = (blockIdx.x * blockDim.x + threadIdx.x) >> 5;
    int l = threadIdx.x & 31;
    if (gw >= M) return;
    float dot = 0.f;
    #pragma unroll
    for (int j = 0; j < 8; j++) {
        int idx = j * 32 + l;
        dot += g_R[(size_t)gw * 256 + idx] * Wr[idx];
    }
    #pragma unroll
    for (int o = 16; o > 0; o >>= 1) dot += __shfl_xor_sync(0xffffffffu, dot, o);
    if (l == 0) out[gw] = wgt[0] * (dot + br[0]);
}

// ---------------- host orchestration ------------------------------------------
extern "C" void kernel_launch(void* const* d_in, const int* in_sizes, int n_in,
                              void* d_out, int out_size)
{
    const float* x     = (const float*)d_in[0];
    const int*   ei    = (const int*)  d_in[1];
    const float* W1    = (const float*)d_in[2];
    const float* b1    = (const float*)d_in[3];
    const float* Wq    = (const float*)d_in[4];
    const float* bq    = (const float*)d_in[5];
    const float* Wk    = (const float*)d_in[6];
    const float* bk    = (const float*)d_in[7];
    const float* gamma = (const float*)d_in[8];
    const float* beta  = (const float*)d_in[9];
    const float* alpha = (const float*)d_in[10];
    const float* Wr    = (const float*)d_in[11];
    const float* br    = (const float*)d_in[12];
    const float* wgt   = (const float*)d_in[13];
    float* out = (float*)d_out;

    const int N = in_sizes[0] / FIN;
    const int E = in_sizes[1] / 2;
    const int* erow = ei;
    const int* ecol = ei + E;

    static cudaStream_t sB = 0, sC = 0;
    static cudaEvent_t evFork = 0, evA0 = 0;
    static cudaEvent_t evG[3], evL[2], evZ[3], evV[3], evMG[3], evD[3], evS[3];
    static bool init_done = false;
    if (!init_done) {
        cudaFuncSetAttribute(mma_gemm<1>, cudaFuncAttributeMaxDynamicSharedMemorySize, 2 * STAGE_BYTES);
        cudaFuncSetAttribute(mma_gemm<2>, cudaFuncAttributeMaxDynamicSharedMemorySize, 2 * STAGE_BYTES);
        cudaFuncSetAttribute(mma_gemm<3>, cudaFuncAttributeMaxDynamicSharedMemorySize, 2 * STAGE_BYTES);
        cudaStreamCreateWithFlags(&sB, cudaStreamNonBlocking);
        cudaStreamCreateWithFlags(&sC, cudaStreamNonBlocking);
        cudaEventCreateWithFlags(&evFork, cudaEventDisableTiming);
        cudaEventCreateWithFlags(&evA0, cudaEventDisableTiming);
        for (int i = 0; i < 3; i++) {
            cudaEventCreateWithFlags(&evG[i], cudaEventDisableTiming);
            cudaEventCreateWithFlags(&evZ[i], cudaEventDisableTiming);
            cudaEventCreateWithFlags(&evV[i], cudaEventDisableTiming);
            cudaEventCreateWithFlags(&evMG[i], cudaEventDisableTiming);
            cudaEventCreateWithFlags(&evD[i], cudaEventDisableTiming);
            cudaEventCreateWithFlags(&evS[i], cudaEventDisableTiming);
        }
        for (int i = 0; i < 2; i++) cudaEventCreateWithFlags(&evL[i], cudaEventDisableTiming);
        init_done = true;
    }

    static float *pR = 0, *pRn = 0, *pC2 = 0;
    static bf16 *pRh = 0, *pRl = 0, *pRTh = 0, *pRTl = 0, *pW2Th = 0, *pW2Tl = 0,
                *pxh = 0, *pxl = 0, *pW1Th = 0, *pW1Tl = 0;
    if (!pRn) {
        cudaGetSymbolAddress((void**)&pR,    g_R);
        cudaGetSymbolAddress((void**)&pRn,   g_Rn);
        cudaGetSymbolAddress((void**)&pC2,   g_c2);
        cudaGetSymbolAddress((void**)&pRh,   g_Rh);
        cudaGetSymbolAddress((void**)&pRl,   g_Rl);
        cudaGetSymbolAddress((void**)&pRTh,  g_RTh);
        cudaGetSymbolAddress((void**)&pRTl,  g_RTl);
        cudaGetSymbolAddress((void**)&pW2Th, g_W2Th);
        cudaGetSymbolAddress((void**)&pW2Tl, g_W2Tl);
        cudaGetSymbolAddress((void**)&pxh,   g_xh);
        cudaGetSymbolAddress((void**)&pxl,   g_xl);
        cudaGetSymbolAddress((void**)&pW1Th, g_W1Th);
        cudaGetSymbolAddress((void**)&pW1Tl, g_W1Tl);
    }

    const int mtiles = (N + 127) / 128;
    const int tgrid = (N * 32 + 255) / 256;
    const int nb1 = (N + 1023) / 1024;

    // ---- fork streams into the capture ----
    cudaEventRecord(evFork, 0);
    cudaStreamWaitEvent(sB, evFork, 0);
    cudaStreamWaitEvent(sC, evFork, 0);

    // CSR build on stream B
    zero_i2     <<<(N + 255) / 256, 256, 0, sB>>>(N);
    cnt_deg     <<<(E + 255) / 256, 256, 0, sB>>>(ecol, E);
    invsqrt_k   <<<(N + 255) / 256, 256, 0, sB>>>(N);
    scan1       <<<nb1, 256, 0, sB>>>(N);
    scan2       <<<1, 128, 0, sB>>>(nb1);
    scan3       <<<(N + 255) / 256, 256, 0, sB>>>(N, E);
    edge_scatter<<<(E + 255) / 256, 256, 0, sB>>>(erow, ecol, E);

    // constants on stream C (weights only)
    build_const<<<256, 256, 0, sC>>>(Wk, Wq, bk, bq);

    // ---- stream A: input GEMM via tensor cores ----
    build_xplanes<<<(N * K1P + 255) / 256, 256>>>(x, N);
    build_w1T<<<(H * K1P + 255) / 256, 256>>>(W1);
    mma_gemm<3><<<dim3(4, mtiles, 1), 256, 2 * STAGE_BYTES>>>(
        pxh, pxl, K1P, pW1Th, pW1Tl, K1P, N, K1P, K1P, b1, nullptr, 0, 0.f);
    cudaEventRecord(evA0, 0);
    {
        dim3 g((N + 31) / 32, 8), b(32, 8);
        transpose2_bf16<<<g, b>>>(pRh, pRl, pRTh, pRTl, N, 256, N);
    }

    cudaStreamWaitEvent(sB, evA0, 0);
    cudaStreamWaitEvent(sC, evA0, 0);
    readout0<<<tgrid, 256, 0, sC>>>(Wr, br, wgt, out, N);

    for (int it = 0; it < 3; it++) {
        // ---- stream B: gather into Gn ---------------------------------------
        if (it > 0) cudaStreamWaitEvent(sB, evL[it - 1], 0);
        gcn_gather_f16<<<(N + 7) / 8, 256, 0, sB>>>(N);
        cudaEventRecord(evG[it], sB);

        // ---- stream A: zero -> G = R^T R (symmetric) -> mirror --------------
        zero2_k<<<256, 256>>>();
        cudaEventRecord(evZ[it], 0);
        {
            int zchunks = (N + 2047) / 2048;
            mma_gemm<2><<<dim3(6, 1, zchunks), 256, 2 * STAGE_BYTES>>>(
                pRTh, pRTl, N, pRTh, pRTl, N, 256, N, 2048, nullptr, nullptr, 1, 0.f);
        }
        mirror_G<<<64, 256>>>();
        cudaEventRecord(evMG[it], 0);

        // ---- stream C: vsum -> pre_den -> den_p; then stats2 (needs G) ------
        cudaStreamWaitEvent(sC, evZ[it], 0);
        vsum_k<<<(N + 127) / 128, 256, 0, sC>>>(N);
        cudaEventRecord(evV[it], sC);
        pre_den<<<1, 256, 0, sC>>>(Wk, Wq, bk, bq, (float)N);
        den_p<<<tgrid, 256, 0, sC>>>(N);
        cudaEventRecord(evD[it], sC);
        cudaStreamWaitEvent(sC, evMG[it], 0);
        stats2<<<1, 256, 0, sC>>>(bk, bq, (float)N);
        cudaEventRecord(evS[it], sC);

        // ---- stream A: W2 = Cqk G + wb (x) vsum (needs G mirrored + vsum) ---
        cudaStreamWaitEvent(0, evV[it], 0);
        small_w2<<<dim3(4, 4), 256>>>();

        // ---- attn: Rn = ((R@W2 + c2)*s + vsum) / (s*denp + N) ---------------
        cudaStreamWaitEvent(0, evD[it], 0);
        cudaStreamWaitEvent(0, evS[it], 0);
        mma_gemm<1><<<dim3(4, mtiles, 1), 256, 2 * STAGE_BYTES>>>(
            pRh, pRl, 256, pW2Th, pW2Tl, 256, N, 256, 256, pC2, pRn, 0, (float)N);

        // ---- join gather, blend + LN ----------------------------------------
        cudaStreamWaitEvent(0, evG[it], 0);
        blend_ln<<<(N + 31) / 32, 256>>>(alpha, gamma, beta, Wr, br, wgt,
                                         it + 1, out, N, it < 2 ? 1 : 0);
        if (it < 2) cudaEventRecord(evL[it], 0);
    }
}

// round 16
// speedup vs baseline: 1.0397x; 1.0397x over previous
#include <cuda_runtime.h>
#include <cuda_bf16.h>
#include <cuda_fp16.h>
#include <math.h>
#include <stdint.h>

#define H 256
#define FIN 58
#define K1P 64
#define N_MAX 100000
#define E_MAX 3200000

typedef __nv_bfloat16 bf16;

// ---------------- scratch (device globals; no allocation allowed) ------------
__device__ float  g_R  [(size_t)N_MAX * H];
__device__ float  g_Rn [(size_t)N_MAX * H];      // attention output
__device__ float  g_Gn [(size_t)N_MAX * H];      // gcn output
__device__ bf16   g_Rh [(size_t)N_MAX * H];
__device__ bf16   g_Rl [(size_t)N_MAX * H];
__device__ __half g_Rf [(size_t)N_MAX * H];      // fp16 plane for GCN gather
__device__ bf16   g_RTh[(size_t)H * N_MAX];
__device__ bf16   g_RTl[(size_t)H * N_MAX];
__device__ bf16   g_xh [(size_t)N_MAX * K1P];    // input x split planes (K padded 64)
__device__ bf16   g_xl [(size_t)N_MAX * K1P];
__device__ bf16   g_W1Th[H * K1P];               // W1^T split planes
__device__ bf16   g_W1Tl[H * K1P];
__device__ float  g_kv [H * H];                  // G = R^T R (fp32, atomics)
__device__ float  g_kvm[H * H];                  // kv  = Wk^T G + bk (x) vsum
__device__ float  g_qv [H * H];                  // qv  = Wq^T G + bq (x) vsum
__device__ bf16   g_W2Th[H * H];                 // W2^T split planes (W2 = Wq @ kv)
__device__ bf16   g_W2Tl[H * H];
__device__ float  g_ksum[H];
__device__ float  g_qsum[H];
__device__ float  g_u  [H];                      // u = Wq @ ksum
__device__ float  g_c2 [H];                      // c2[d] = bq . kv[:,d]
__device__ float  g_scal[4];                     // [k2, q2, s, c_den]
__device__ float  g_dinv[N_MAX];
__device__ float  g_denp[N_MAX];                 // denp = R.u + c_den (no s)
__device__ float  g_stats[2 + 2 * H];            // vsum at [2+256..2+511]
// CSR structures
__device__ int    g_degi[N_MAX];
__device__ int    g_cur [N_MAX];
__device__ int    g_off [N_MAX + 1];
__device__ int    g_bsum[128];
__device__ int    g_esrc[E_MAX];
__device__ float  g_ew  [E_MAX];

// ---------------- PTX helpers --------------------------------------------------
__device__ __forceinline__ uint32_t smem_u32(const void* p) {
    uint32_t a;
    asm("{ .reg .u64 t; cvta.to.shared.u64 t, %1; cvt.u32.u64 %0, t; }" : "=r"(a) : "l"(p));
    return a;
}
__device__ __forceinline__ void ldsm4(uint32_t* r, uint32_t addr) {
    asm volatile("ldmatrix.sync.aligned.m8n8.x4.shared.b16 {%0,%1,%2,%3}, [%4];"
                 : "=r"(r[0]), "=r"(r[1]), "=r"(r[2]), "=r"(r[3]) : "r"(addr));
}
__device__ __forceinline__ void mma16816(float* c, const uint32_t* a, uint32_t b0, uint32_t b1) {
    asm volatile("mma.sync.aligned.m16n8k16.row.col.f32.bf16.bf16.f32 "
                 "{%0,%1,%2,%3}, {%4,%5,%6,%7}, {%8,%9}, {%0,%1,%2,%3};"
                 : "+f"(c[0]), "+f"(c[1]), "+f"(c[2]), "+f"(c[3])
                 : "r"(a[0]), "r"(a[1]), "r"(a[2]), "r"(a[3]), "r"(b0), "r"(b1));
}
__device__ __forceinline__ void cpa16(uint32_t dst, const void* src, bool pred) {
    int sz = pred ? 16 : 0;
    asm volatile("cp.async.cg.shared.global [%0], [%1], 16, %2;"
                 :: "r"(dst), "l"(src), "r"(sz));
}
#define CP_COMMIT() asm volatile("cp.async.commit_group;" ::: "memory")
#define SW128(o) ((o) ^ (((o) >> 3) & 0x70))

// ---------------- tiny utility kernels ---------------------------------------
__global__ void zero2_k() {
    int i = blockIdx.x * blockDim.x + threadIdx.x;
    if (i < H * H) g_kv[i] = 0.f;
    if (i < 2 + 2 * H) g_stats[i] = 0.f;
}
__global__ void mirror_G() {
    int i = blockIdx.x * blockDim.x + threadIdx.x;
    if (i >= 128 * 128) return;
    int r = 128 + (i >> 7), c = i & 127;
    g_kv[r * H + c] = g_kv[c * H + r];
}
__global__ void zero_i2(int n) {
    int i = blockIdx.x * blockDim.x + threadIdx.x;
    if (i < n) { g_degi[i] = 0; g_cur[i] = 0; }
}
__global__ void cnt_deg(const int* __restrict__ col, int E) {
    int i = blockIdx.x * blockDim.x + threadIdx.x;
    if (i < E) atomicAdd(&g_degi[col[i]], 1);
}
__global__ void invsqrt_k(int n) {
    int i = blockIdx.x * blockDim.x + threadIdx.x;
    if (i < n) {
        int d = g_degi[i];
        g_dinv[i] = (d > 0) ? rsqrtf((float)d) : 0.f;
    }
}
__global__ __launch_bounds__(256) void scan1(int n) {
    __shared__ int s[256];
    int b = blockIdx.x, t = threadIdx.x;
    int base = b * 1024 + t * 4;
    int v0 = 0, v1 = 0, v2 = 0, v3 = 0;
    if (base + 0 < n) v0 = g_degi[base + 0];
    if (base + 1 < n) v1 = g_degi[base + 1];
    if (base + 2 < n) v2 = g_degi[base + 2];
    if (base + 3 < n) v3 = g_degi[base + 3];
    int tsum = v0 + v1 + v2 + v3;
    s[t] = tsum;
    __syncthreads();
    for (int o = 1; o < 256; o <<= 1) {
        int x = 0;
        if (t >= o) x = s[t - o];
        __syncthreads();
        s[t] += x;
        __syncthreads();
    }
    int ex = s[t] - tsum;
    if (base + 0 < n) g_off[base + 0] = ex;
    if (base + 1 < n) g_off[base + 1] = ex + v0;
    if (base + 2 < n) g_off[base + 2] = ex + v0 + v1;
    if (base + 3 < n) g_off[base + 3] = ex + v0 + v1 + v2;
    if (t == 255) g_bsum[b] = s[255];
}
__global__ void scan2(int nb) {
    __shared__ int s[128];
    int t = threadIdx.x;
    int v = (t < nb) ? g_bsum[t] : 0;
    s[t] = v;
    __syncthreads();
    for (int o = 1; o < 128; o <<= 1) {
        int x = 0;
        if (t >= o) x = s[t - o];
        __syncthreads();
        s[t] += x;
        __syncthreads();
    }
    g_bsum[t] = s[t] - v;
}
__global__ void scan3(int n, int E) {
    int i = blockIdx.x * blockDim.x + threadIdx.x;
    if (i < n) g_off[i] += g_bsum[i >> 10];
    if (i == 0) g_off[n] = E;
}
__global__ void edge_scatter(const int* __restrict__ erow, const int* __restrict__ ecol, int E) {
    int e = blockIdx.x * blockDim.x + threadIdx.x;
    if (e >= E) return;
    int c = ecol[e], r = erow[e];
    int pos = g_off[c] + atomicAdd(&g_cur[c], 1);
    g_esrc[pos] = r;
    g_ew[pos] = g_dinv[r] * g_dinv[c];
}

__device__ __forceinline__ void split_store(float v, bf16* ph, bf16* pl, size_t idx) {
    bf16 h = __float2bfloat16(v);
    ph[idx] = h;
    pl[idx] = __float2bfloat16(v - __bfloat162float(h));
}
__global__ void build_xplanes(const float* __restrict__ x, int n) {
    int idx = blockIdx.x * blockDim.x + threadIdx.x;
    if (idx >= n * K1P) return;
    int r = idx >> 6, c = idx & 63;
    float v = (c < FIN) ? x[(size_t)r * FIN + c] : 0.f;
    split_store(v, g_xh, g_xl, idx);
}
__global__ void build_w1T(const float* __restrict__ W1) {
    int idx = blockIdx.x * blockDim.x + threadIdx.x;
    if (idx >= H * K1P) return;
    int nn = idx >> 6, k = idx & 63;
    float v = (k < FIN) ? W1[k * H + nn] : 0.f;
    split_store(v, g_W1Th, g_W1Tl, idx);
}
__global__ void transpose2_bf16(const bf16* __restrict__ ih, const bf16* __restrict__ il,
                                bf16* __restrict__ oh, bf16* __restrict__ ol,
                                int rows, int istride, int ostride) {
    __shared__ bf16 th[32][33], tl[32][33];
    int r0 = blockIdx.x * 32, c0 = blockIdx.y * 32;
    for (int i = threadIdx.y; i < 32; i += 8) {
        int r = r0 + i, c = c0 + threadIdx.x;
        bf16 zh = __float2bfloat16(0.f);
        th[i][threadIdx.x] = (r < rows) ? ih[(size_t)r * istride + c] : zh;
        tl[i][threadIdx.x] = (r < rows) ? il[(size_t)r * istride + c] : zh;
    }
    __syncthreads();
    for (int i = threadIdx.y; i < 32; i += 8) {
        int oc = r0 + threadIdx.x, orow = c0 + i;
        if (oc < rows) {
            oh[(size_t)orow * ostride + oc] = th[threadIdx.x][i];
            ol[(size_t)orow * ostride + oc] = tl[threadIdx.x][i];
        }
    }
}

// ---------------- mma.sync split-bf16 GEMM, 2-stage cp.async pipeline ---------
// EPI 1: attn  v = ((acc + c2[c])*s + vsum[c]) / (s*denp[r] + fN)
// EPI 2: atomic fp32 into g_kv; gsym=1 remaps 6 blocks to the symmetric set.
// EPI 3: input GEMM: relu(acc + b1[c]) -> R, Rh, Rl, Rf
#define STAGE_BYTES 49152
template <int EPI>
__global__ __launch_bounds__(256, 2) void mma_gemm(
    const bf16* __restrict__ Ah_, const bf16* __restrict__ Al_, int lda,
    const bf16* __restrict__ Bh_, const bf16* __restrict__ Bl_, int ldb,
    int Mrows, int Ktot, int kchunk,
    const float* __restrict__ e0,
    float* __restrict__ outf, int gsym, float fN)
{
    extern __shared__ char smem[];
    const int tid = threadIdx.x, wid = tid >> 5, lane = tid & 31;
    const int wm = (wid & 3) * 32;
    const int wn = (wid >> 2) * 32;
    int bx = blockIdx.x, by = blockIdx.y;
    if (gsym) {
        if (bx >= 4) { by = 1; bx = bx - 2; } else { by = 0; }
    }
    const int row0 = by * 128;
    const int ncol0 = bx * 64;
    const int k0 = blockIdx.z * kchunk;
    int kend = k0 + kchunk; if (kend > Ktot) kend = Ktot;
    const uint32_t sbase = smem_u32(smem);

    auto fill = [&](int stage, int ks) {
        uint32_t sa = sbase + stage * STAGE_BYTES;
        #pragma unroll
        for (int it = 0; it < 4; it++) {
            int ch = tid + it * 256;
            int r = ch >> 3, c8 = ch & 7;
            int g = row0 + r;
            int kb = ks + c8 * 8;
            uint32_t off = SW128((uint32_t)(r * 128 + c8 * 16));
            bool p = (g < Mrows) && (kb + 8 <= kend);
            const bf16* ph = p ? &Ah_[(size_t)g * lda + kb] : Ah_;
            const bf16* pl = p ? &Al_[(size_t)g * lda + kb] : Al_;
            cpa16(sa + off, ph, p);
            cpa16(sa + 16384 + off, pl, p);
        }
        #pragma unroll
        for (int it = 0; it < 2; it++) {
            int ch = tid + it * 256;
            int r = ch >> 3, c8 = ch & 7;
            int gn = ncol0 + r;
            int kb = ks + c8 * 8;
            uint32_t off = SW128((uint32_t)(r * 128 + c8 * 16));
            bool p = (kb + 8 <= kend);
            const bf16* ph = p ? &Bh_[(size_t)gn * ldb + kb] : Bh_;
            const bf16* pl = p ? &Bl_[(size_t)gn * ldb + kb] : Bl_;
            cpa16(sa + 32768 + off, ph, p);
            cpa16(sa + 40960 + off, pl, p);
        }
    };

    float acc[2][4][4] = {};
    int stage = 0;
    fill(0, k0);
    CP_COMMIT();

    for (int ks = k0; ks < kend; ks += 64) {
        int nxt = ks + 64;
        if (nxt < kend) {
            fill(stage ^ 1, nxt);
            CP_COMMIT();
            asm volatile("cp.async.wait_group 1;" ::: "memory");
        } else {
            asm volatile("cp.async.wait_group 0;" ::: "memory");
        }
        __syncthreads();

        uint32_t base = sbase + stage * STAGE_BYTES;
        #pragma unroll
        for (int kc = 0; kc < 4; kc++) {
            uint32_t ah[2][4], al[2][4], bh[2][4], bl[2][4];
            #pragma unroll
            for (int mt = 0; mt < 2; mt++) {
                uint32_t off = SW128((uint32_t)((wm + mt * 16 + (lane & 15)) * 128 +
                                                (kc * 16 + (lane >> 4) * 8) * 2));
                ldsm4(ah[mt], base + off);
                ldsm4(al[mt], base + 16384 + off);
            }
            #pragma unroll
            for (int ntp = 0; ntp < 2; ntp++) {
                uint32_t off = SW128((uint32_t)((wn + ntp * 16 + ((lane >> 4) & 1) * 8 + (lane & 7)) * 128 +
                                                (kc * 16 + ((lane >> 3) & 1) * 8) * 2));
                ldsm4(bh[ntp], base + 32768 + off);
                ldsm4(bl[ntp], base + 40960 + off);
            }
            #pragma unroll
            for (int mt = 0; mt < 2; mt++)
                #pragma unroll
                for (int nt = 0; nt < 4; nt++) {
                    uint32_t b0h = bh[nt >> 1][(nt & 1) * 2], b1h = bh[nt >> 1][(nt & 1) * 2 + 1];
                    uint32_t b0l = bl[nt >> 1][(nt & 1) * 2], b1l = bl[nt >> 1][(nt & 1) * 2 + 1];
                    mma16816(acc[mt][nt], ah[mt], b0h, b1h);
                    mma16816(acc[mt][nt], ah[mt], b0l, b1l);
                    mma16816(acc[mt][nt], al[mt], b0h, b1h);
                }
        }
        __syncthreads();
        stage ^= 1;
    }

    if (EPI == 1) {
        float s_val = g_scal[2];
        #pragma unroll
        for (int mt = 0; mt < 2; mt++)
            #pragma unroll
            for (int rg = 0; rg < 4; rg++) {
                int r = row0 + wm + mt * 16 + (lane >> 2) + ((rg >> 1) & 1) * 8;
                if (r >= Mrows) continue;
                float id = 1.0f / (s_val * g_denp[r] + fN);
                #pragma unroll
                for (int nt = 0; nt < 4; nt++) {
                    int c = ncol0 + wn + nt * 8 + (lane & 3) * 2 + (rg & 1);
                    float v = ((acc[mt][nt][rg] + e0[c]) * s_val + g_stats[2 + H + c]) * id;
                    outf[(size_t)r * H + c] = v;
                }
            }
    } else if (EPI == 3) {
        #pragma unroll
        for (int mt = 0; mt < 2; mt++)
            #pragma unroll
            for (int rg = 0; rg < 4; rg++) {
                int r = row0 + wm + mt * 16 + (lane >> 2) + ((rg >> 1) & 1) * 8;
                if (r >= Mrows) continue;
                #pragma unroll
                for (int nt = 0; nt < 4; nt++) {
                    int c = ncol0 + wn + nt * 8 + (lane & 3) * 2 + (rg & 1);
                    float v = fmaxf(acc[mt][nt][rg] + e0[c], 0.f);
                    size_t idx = (size_t)r * H + c;
                    g_R[idx] = v;
                    split_store(v, g_Rh, g_Rl, idx);
                    g_Rf[idx] = __float2half(v);
                }
            }
    } else {
        #pragma unroll
        for (int mt = 0; mt < 2; mt++)
            #pragma unroll
            for (int rg = 0; rg < 4; rg++) {
                int r = row0 + wm + mt * 16 + (lane >> 2) + ((rg >> 1) & 1) * 8;
                if (r >= Mrows) continue;
                #pragma unroll
                for (int nt = 0; nt < 4; nt++) {
                    int c = ncol0 + wn + nt * 8 + (lane & 3) * 2 + (rg & 1);
                    atomicAdd(&g_kv[(size_t)r * H + c], acc[mt][nt][rg]);
                }
            }
    }
}

// ---------------- vsum: colsum of R ------------------------------------------
__global__ __launch_bounds__(256) void vsum_k(int M) {
    int t = threadIdx.x;
    int r0 = blockIdx.x * 128;
    int rend = r0 + 128; if (rend > M) rend = M;
    float vs = 0.f;
    for (int r = r0; r < rend; r++) vs += g_R[(size_t)r * 256 + t];
    atomicAdd(&g_stats[2 + 256 + t], vs);
}

// ---- pre_den: ksum, qsum, u, c_den — needs ONLY vsum (no G) ------------------
__global__ __launch_bounds__(256) void pre_den(
    const float* __restrict__ Wk, const float* __restrict__ Wq,
    const float* __restrict__ bk, const float* __restrict__ bq, float fN)
{
    __shared__ float sks[256];
    int t = threadIdx.x;
    float ks = 0.f, qs = 0.f;
    for (int i = 0; i < 256; i++) {
        float v = g_stats[2 + 256 + i];
        ks += v * Wk[i * 256 + t];
        qs += v * Wq[i * 256 + t];
    }
    ks += fN * bk[t];
    qs += fN * bq[t];
    g_ksum[t] = ks;
    g_qsum[t] = qs;
    sks[t] = ks;
    __syncthreads();
    float u = 0.f;
    for (int m = 0; m < 256; m++) u += Wq[t * 256 + m] * sks[m];
    g_u[t] = u;
    __shared__ float red[256];
    red[t] = bq[t] * sks[t];
    __syncthreads();
    for (int o = 128; o > 0; o >>= 1) {
        if (t < o) red[t] += red[t + o];
        __syncthreads();
    }
    if (t == 0) g_scal[3] = red[0];
}

// denp_n = R_n . u + c_den  (no s; folded into attn epilogue)
__global__ void den_p(int M) {
    int gw = (blockIdx.x * blockDim.x + threadIdx.x) >> 5;
    int l = threadIdx.x & 31;
    if (gw >= M) return;
    size_t base = (size_t)gw * 256;
    float sum = 0.f;
    #pragma unroll
    for (int j = 0; j < 8; j++) {
        int idx = j * 32 + l;
        sum += g_R[base + idx] * g_u[idx];
    }
    #pragma unroll
    for (int o = 16; o > 0; o >>= 1) sum += __shfl_xor_sync(0xffffffffu, sum, o);
    if (l == 0) g_denp[gw] = sum + g_scal[3];
}

// ---- small fp32 GEMMs over 256x256 -------------------------------------------
// z=0: kv = Wk^T G + bk (x) vsum ; z=1: qv = Wq^T G + bq (x) vsum
__global__ __launch_bounds__(256) void small_tmm(
    const float* __restrict__ Wk, const float* __restrict__ Wq,
    const float* __restrict__ bk, const float* __restrict__ bq)
{
    const float* W = blockIdx.z ? Wq : Wk;
    const float* b = blockIdx.z ? bq : bk;
    float* C = blockIdx.z ? g_qv : g_kvm;
    const int m0 = blockIdx.y * 64, d0 = blockIdx.x * 64;
    __shared__ float sW[8][64], sG[8][64];
    const int tid = threadIdx.x;
    const int tr = tid >> 4, tc = tid & 15;
    float acc[4][4] = {};
    for (int k0 = 0; k0 < 256; k0 += 8) {
        #pragma unroll
        for (int t = tid; t < 512; t += 256) {
            int i = t >> 6, c = t & 63;
            sW[i][c] = W[(k0 + i) * 256 + m0 + c];
            sG[i][c] = g_kv[(k0 + i) * 256 + d0 + c];
        }
        __syncthreads();
        #pragma unroll
        for (int kk = 0; kk < 8; kk++) {
            float a[4], bb[4];
            #pragma unroll
            for (int i = 0; i < 4; i++) a[i] = sW[kk][tr * 4 + i];
            #pragma unroll
            for (int j = 0; j < 4; j++) bb[j] = sG[kk][tc * 4 + j];
            #pragma unroll
            for (int i = 0; i < 4; i++)
                #pragma unroll
                for (int j = 0; j < 4; j++)
                    acc[i][j] += a[i] * bb[j];
        }
        __syncthreads();
    }
    #pragma unroll
    for (int i = 0; i < 4; i++) {
        int m = m0 + tr * 4 + i;
        #pragma unroll
        for (int j = 0; j < 4; j++) {
            int d = d0 + tc * 4 + j;
            C[m * 256 + d] = acc[i][j] + b[m] * g_stats[2 + 256 + d];
        }
    }
}

// W2 = Wq @ kv; write W2^T split planes directly
__global__ __launch_bounds__(256) void small_mm(const float* __restrict__ Wq) {
    const int i0 = blockIdx.y * 64, d0 = blockIdx.x * 64;
    __shared__ float sA[8][64], sB[8][64];
    const int tid = threadIdx.x;
    const int tr = tid >> 4, tc = tid & 15;
    float acc[4][4] = {};
    for (int k0 = 0; k0 < 256; k0 += 8) {
        #pragma unroll
        for (int t = tid; t < 512; t += 256) {
            int ii = t >> 3, kk = t & 7;
            sA[kk][ii] = Wq[(i0 + ii) * 256 + k0 + kk];
        }
        #pragma unroll
        for (int t = tid; t < 512; t += 256) {
            int kk = t >> 6, d = t & 63;
            sB[kk][d] = g_kvm[(k0 + kk) * 256 + d0 + d];
        }
        __syncthreads();
        #pragma unroll
        for (int kk = 0; kk < 8; kk++) {
            float a[4], bb[4];
            #pragma unroll
            for (int i = 0; i < 4; i++) a[i] = sA[kk][tr * 4 + i];
            #pragma unroll
            for (int j = 0; j < 4; j++) bb[j] = sB[kk][tc * 4 + j];
            #pragma unroll
            for (int i = 0; i < 4; i++)
                #pragma unroll
                for (int j = 0; j < 4; j++)
                    acc[i][j] += a[i] * bb[j];
        }
        __syncthreads();
    }
    #pragma unroll
    for (int i = 0; i < 4; i++)
        #pragma unroll
        for (int j = 0; j < 4; j++)
            split_store(acc[i][j], g_W2Th, g_W2Tl,
                        (size_t)(d0 + tc * 4 + j) * 256 + (i0 + tr * 4 + i));
}

// one block: k2, q2 -> s; c2 = bq @ kvm
__global__ __launch_bounds__(256) void small_stats2(
    const float* __restrict__ Wk, const float* __restrict__ Wq,
    const float* __restrict__ bk, const float* __restrict__ bq)
{
    int m = threadIdx.x;
    float pk = 0.f, pq = 0.f;
    for (int j = 0; j < 256; j++) {
        pk += g_kvm[m * 256 + j] * Wk[j * 256 + m];
        pq += g_qv [m * 256 + j] * Wq[j * 256 + m];
    }
    pk += bk[m] * g_ksum[m];
    pq += bq[m] * g_qsum[m];
    __shared__ float rk[256], rq[256];
    rk[m] = pk; rq[m] = pq;
    __syncthreads();
    for (int o = 128; o > 0; o >>= 1) {
        if (m < o) { rk[m] += rk[m + o]; rq[m] += rq[m + o]; }
        __syncthreads();
    }
    if (m == 0) {
        g_scal[0] = rk[0];
        g_scal[1] = rq[0];
        g_scal[2] = rsqrtf(rk[0]) * rsqrtf(rq[0]);
    }
    float c = 0.f;
    for (int j = 0; j < 256; j++) c += bq[j] * g_kvm[j * 256 + m];
    g_c2[m] = c;
}

// ---------------- GCN gather (fp16 plane, 256-dim, writes Gn, unroll 4) -------
__global__ __launch_bounds__(256) void gcn_gather_f16(int Nn) {
    int warp = (blockIdx.x * blockDim.x + threadIdx.x) >> 5;
    if (warp >= Nn) return;
    int l = threadIdx.x & 31;
    int beg = g_off[warp], end = g_off[warp + 1];
    float a[8] = {};
    const int4* Rb = (const int4*)g_Rf;
    int e = beg;
    for (; e + 4 <= end; e += 4) {
        int s0 = __ldg(&g_esrc[e]);
        int s1 = __ldg(&g_esrc[e + 1]);
        int s2 = __ldg(&g_esrc[e + 2]);
        int s3 = __ldg(&g_esrc[e + 3]);
        float w0 = __ldg(&g_ew[e]);
        float w1 = __ldg(&g_ew[e + 1]);
        float w2 = __ldg(&g_ew[e + 2]);
        float w3 = __ldg(&g_ew[e + 3]);
        int4 p0 = __ldg(&Rb[(size_t)s0 * 32 + l]);
        int4 p1 = __ldg(&Rb[(size_t)s1 * 32 + l]);
        int4 p2 = __ldg(&Rb[(size_t)s2 * 32 + l]);
        int4 p3 = __ldg(&Rb[(size_t)s3 * 32 + l]);
        const __half2* h0 = (const __half2*)&p0;
        const __half2* h1 = (const __half2*)&p1;
        const __half2* h2 = (const __half2*)&p2;
        const __half2* h3 = (const __half2*)&p3;
        #pragma unroll
        for (int j = 0; j < 4; j++) {
            float2 v0 = __half22float2(h0[j]);
            float2 v1 = __half22float2(h1[j]);
            float2 v2 = __half22float2(h2[j]);
            float2 v3 = __half22float2(h3[j]);
            a[2 * j]     += w0 * v0.x + w1 * v1.x + w2 * v2.x + w3 * v3.x;
            a[2 * j + 1] += w0 * v0.y + w1 * v1.y + w2 * v2.y + w3 * v3.y;
        }
    }
    for (; e < end; e++) {
        int s0 = __ldg(&g_esrc[e]);
        float w0 = __ldg(&g_ew[e]);
        int4 p0 = __ldg(&Rb[(size_t)s0 * 32 + l]);
        const __half2* h0 = (const __half2*)&p0;
        #pragma unroll
        for (int j = 0; j < 4; j++) {
            float2 v0 = __half22float2(h0[j]);
            a[2 * j]     += w0 * v0.x;
            a[2 * j + 1] += w0 * v0.y;
        }
    }
    float* dst = &g_Gn[(size_t)warp * 256 + l * 8];
    *(float4*)&dst[0] = *(float4*)&a[0];
    *(float4*)&dst[4] = *(float4*)&a[4];
}

// ---------------- blend + LayerNorm + RT planes + readout ---------------------
__global__ __launch_bounds__(256) void blend_ln(
    const float* __restrict__ alpha_p,
    const float* __restrict__ gamma, const float* __restrict__ beta,
    const float* __restrict__ Wr, const float* __restrict__ br,
    const float* __restrict__ wgt, int sidx,
    float* __restrict__ out, int M, int writeRT)
{
    __shared__ bf16 sh[32][260];
    __shared__ bf16 sl[32][260];
    const int n0 = blockIdx.x * 32;
    const int wid = threadIdx.x >> 5, l = threadIdx.x & 31;
    const float al = alpha_p[0];
    const float* wr = Wr + sidx * 256;

    #pragma unroll
    for (int i = 0; i < 4; i++) {
        int nl = wid * 4 + i;
        int node = n0 + nl;
        if (node < M) {
            size_t base = (size_t)node * 256;
            float h[8]; float sum = 0.f, sq = 0.f;
            #pragma unroll
            for (int j = 0; j < 8; j++) {
                int idx = j * 32 + l;
                float v = al * (g_Rn[base + idx] + g_Gn[base + idx]) + (1.f - al) * g_R[base + idx];
                h[j] = v; sum += v; sq += v * v;
            }
            #pragma unroll
            for (int o = 16; o > 0; o >>= 1) {
                sum += __shfl_xor_sync(0xffffffffu, sum, o);
                sq  += __shfl_xor_sync(0xffffffffu, sq, o);
            }
            float mu  = sum * (1.f / 256.f);
            float var = sq * (1.f / 256.f) - mu * mu;
            float rstd = rsqrtf(var + 1e-5f);
            float dot = 0.f;
            #pragma unroll
            for (int j = 0; j < 8; j++) {
                int idx = j * 32 + l;
                float y = (h[j] - mu) * rstd * gamma[idx] + beta[idx];
                g_R[base + idx] = y;
                bf16 yh = __float2bfloat16(y);
                bf16 yl = __float2bfloat16(y - __bfloat162float(yh));
                g_Rh[base + idx] = yh;
                g_Rl[base + idx] = yl;
                g_Rf[base + idx] = __float2half(y);
                sh[nl][idx] = yh;
                sl[nl][idx] = yl;
                dot += y * wr[idx];
            }
            #pragma unroll
            for (int o = 16; o > 0; o >>= 1) dot += __shfl_xor_sync(0xffffffffu, dot, o);
            if (l == 0) out[node] += wgt[sidx] * (dot + br[sidx]);
        }
    }

    if (writeRT) {
        __syncthreads();
        int d = threadIdx.x;
        size_t Nn = (size_t)M;
        if (n0 + 32 <= M && ((Nn * 2) & 15) == 0) {
            uint32_t ph[16], pl[16];
            #pragma unroll
            for (int p = 0; p < 16; p++) {
                uint32_t h0 = __bfloat16_as_ushort(sh[p * 2][d]);
                uint32_t h1 = __bfloat16_as_ushort(sh[p * 2 + 1][d]);
                uint32_t l0 = __bfloat16_as_ushort(sl[p * 2][d]);
                uint32_t l1 = __bfloat16_as_ushort(sl[p * 2 + 1][d]);
                ph[p] = h0 | (h1 << 16);
                pl[p] = l0 | (l1 << 16);
            }
            size_t gb = (size_t)d * Nn + n0;
            #pragma unroll
            for (int q = 0; q < 4; q++) {
                *(int4*)&g_RTh[gb + q * 8] = *(int4*)&ph[q * 4];
                *(int4*)&g_RTl[gb + q * 8] = *(int4*)&pl[q * 4];
            }
        } else {
            for (int nl = 0; nl < 32; nl++) {
                if (n0 + nl < M) {
                    g_RTh[(size_t)d * Nn + n0 + nl] = sh[nl][d];
                    g_RTl[(size_t)d * Nn + n0 + nl] = sl[nl][d];
                }
            }
        }
    }
}

__global__ void readout0(const float* __restrict__ Wr, const float* __restrict__ br,
                         const float* __restrict__ wgt, float* __restrict__ out, int M)
{
    int gw = (blockIdx.x * blockDim.x + threadIdx.x) >> 5;
    int l = threadIdx.x & 31;
    if (gw >= M) return;
    float dot = 0.f;
    #pragma unroll
    for (int j = 0; j < 8; j++) {
        int idx = j * 32 + l;
        dot += g_R[(size_t)gw * 256 + idx] * Wr[idx];
    }
    #pragma unroll
    for (int o = 16; o > 0; o >>= 1) dot += __shfl_xor_sync(0xffffffffu, dot, o);
    if (l == 0) out[gw] = wgt[0] * (dot + br[0]);
}

// ---------------- host orchestration ------------------------------------------
extern "C" void kernel_launch(void* const* d_in, const int* in_sizes, int n_in,
                              void* d_out, int out_size)
{
    const float* x     = (const float*)d_in[0];
    const int*   ei    = (const int*)  d_in[1];
    const float* W1    = (const float*)d_in[2];
    const float* b1    = (const float*)d_in[3];
    const float* Wq    = (const float*)d_in[4];
    const float* bq    = (const float*)d_in[5];
    const float* Wk    = (const float*)d_in[6];
    const float* bk    = (const float*)d_in[7];
    const float* gamma = (const float*)d_in[8];
    const float* beta  = (const float*)d_in[9];
    const float* alpha = (const float*)d_in[10];
    const float* Wr    = (const float*)d_in[11];
    const float* br    = (const float*)d_in[12];
    const float* wgt   = (const float*)d_in[13];
    float* out = (float*)d_out;

    const int N = in_sizes[0] / FIN;
    const int E = in_sizes[1] / 2;
    const int* erow = ei;
    const int* ecol = ei + E;

    static cudaStream_t sB = 0, sC = 0;
    static cudaEvent_t evFork = 0, evA0 = 0;
    static cudaEvent_t evG[3], evL[2], evZ[3], evV[3], evM[3], evD[3], evS[3];
    static bool init_done = false;
    if (!init_done) {
        cudaFuncSetAttribute(mma_gemm<1>, cudaFuncAttributeMaxDynamicSharedMemorySize, 2 * STAGE_BYTES);
        cudaFuncSetAttribute(mma_gemm<2>, cudaFuncAttributeMaxDynamicSharedMemorySize, 2 * STAGE_BYTES);
        cudaFuncSetAttribute(mma_gemm<3>, cudaFuncAttributeMaxDynamicSharedMemorySize, 2 * STAGE_BYTES);
        cudaStreamCreateWithFlags(&sB, cudaStreamNonBlocking);
        cudaStreamCreateWithFlags(&sC, cudaStreamNonBlocking);
        cudaEventCreateWithFlags(&evFork, cudaEventDisableTiming);
        cudaEventCreateWithFlags(&evA0, cudaEventDisableTiming);
        for (int i = 0; i < 3; i++) {
            cudaEventCreateWithFlags(&evG[i], cudaEventDisableTiming);
            cudaEventCreateWithFlags(&evZ[i], cudaEventDisableTiming);
            cudaEventCreateWithFlags(&evV[i], cudaEventDisableTiming);
            cudaEventCreateWithFlags(&evM[i], cudaEventDisableTiming);
            cudaEventCreateWithFlags(&evD[i], cudaEventDisableTiming);
            cudaEventCreateWithFlags(&evS[i], cudaEventDisableTiming);
        }
        for (int i = 0; i < 2; i++) cudaEventCreateWithFlags(&evL[i], cudaEventDisableTiming);
        init_done = true;
    }

    static float *pR = 0, *pRn = 0, *pC2 = 0;
    static bf16 *pRh = 0, *pRl = 0, *pRTh = 0, *pRTl = 0, *pW2Th = 0, *pW2Tl = 0,
                *pxh = 0, *pxl = 0, *pW1Th = 0, *pW1Tl = 0;
    if (!pR) {
        cudaGetSymbolAddress((void**)&pR,    g_R);
        cudaGetSymbolAddress((void**)&pRn,   g_Rn);
        cudaGetSymbolAddress((void**)&pC2,   g_c2);
        cudaGetSymbolAddress((void**)&pRh,   g_Rh);
        cudaGetSymbolAddress((void**)&pRl,   g_Rl);
        cudaGetSymbolAddress((void**)&pRTh,  g_RTh);
        cudaGetSymbolAddress((void**)&pRTl,  g_RTl);
        cudaGetSymbolAddress((void**)&pW2Th, g_W2Th);
        cudaGetSymbolAddress((void**)&pW2Tl, g_W2Tl);
        cudaGetSymbolAddress((void**)&pxh,   g_xh);
        cudaGetSymbolAddress((void**)&pxl,   g_xl);
        cudaGetSymbolAddress((void**)&pW1Th, g_W1Th);
        cudaGetSymbolAddress((void**)&pW1Tl, g_W1Tl);
    }

    const int mtiles = (N + 127) / 128;
    const int tgrid = (N * 32 + 255) / 256;
    const int nb1 = (N + 1023) / 1024;

    // ---- fork streams into the capture ----
    cudaEventRecord(evFork, 0);
    cudaStreamWaitEvent(sB, evFork, 0);
    cudaStreamWaitEvent(sC, evFork, 0);

    // CSR build on stream B (overlaps input GEMM)
    zero_i2     <<<(N + 255) / 256, 256, 0, sB>>>(N);
    cnt_deg     <<<(E + 255) / 256, 256, 0, sB>>>(ecol, E);
    invsqrt_k   <<<(N + 255) / 256, 256, 0, sB>>>(N);
    scan1       <<<nb1, 256, 0, sB>>>(N);
    scan2       <<<1, 128, 0, sB>>>(nb1);
    scan3       <<<(N + 255) / 256, 256, 0, sB>>>(N, E);
    edge_scatter<<<(E + 255) / 256, 256, 0, sB>>>(erow, ecol, E);

    // ---- stream A: input GEMM via tensor cores ----
    build_xplanes<<<(N * K1P + 255) / 256, 256>>>(x, N);
    build_w1T<<<(H * K1P + 255) / 256, 256>>>(W1);
    mma_gemm<3><<<dim3(4, mtiles, 1), 256, 2 * STAGE_BYTES>>>(
        pxh, pxl, K1P, pW1Th, pW1Tl, K1P, N, K1P, K1P, b1, nullptr, 0, 0.f);
    cudaEventRecord(evA0, 0);
    readout0<<<tgrid, 256>>>(Wr, br, wgt, out, N);
    {
        dim3 g((N + 31) / 32, 8), b(32, 8);
        transpose2_bf16<<<g, b>>>(pRh, pRl, pRTh, pRTl, N, 256, N);
    }

    cudaStreamWaitEvent(sB, evA0, 0);
    cudaStreamWaitEvent(sC, evA0, 0);

    for (int it = 0; it < 3; it++) {
        // ---- stream B: gather into Gn (fp16 plane) --------------------------
        if (it > 0) cudaStreamWaitEvent(sB, evL[it - 1], 0);
        gcn_gather_f16<<<(N + 7) / 8, 256, 0, sB>>>(N);
        cudaEventRecord(evG[it], sB);

        // ---- stream A: zero -> G = R^T R (symmetric: 6 of 8 blocks) ---------
        zero2_k<<<256, 256>>>();
        cudaEventRecord(evZ[it], 0);

        {
            int zchunks = (N + 2047) / 2048;
            mma_gemm<2><<<dim3(6, 1, zchunks), 256, 2 * STAGE_BYTES>>>(
                pRTh, pRTl, N, pRTh, pRTl, N, 256, N, 2048, nullptr, nullptr, 1, 0.f);
        }
        mirror_G<<<64, 256>>>();

        // ---- stream C: vsum -> pre_den -> den_p (no dependence on G) --------
        cudaStreamWaitEvent(sC, evZ[it], 0);
        vsum_k<<<(N + 127) / 128, 256, 0, sC>>>(N);
        cudaEventRecord(evV[it], sC);
        pre_den<<<1, 256, 0, sC>>>(Wk, Wq, bk, bq, (float)N);
        den_p<<<tgrid, 256, 0, sC>>>(N);
        cudaEventRecord(evD[it], sC);

        // ---- stream A: kv/qv from G (needs vsum) ----------------------------
        cudaStreamWaitEvent(0, evV[it], 0);
        small_tmm<<<dim3(4, 4, 2), 256>>>(Wk, Wq, bk, bq);
        cudaEventRecord(evM[it], 0);

        // ---- stream C: stats (k2,q2,s,c2) after small_tmm + pre_den ---------
        cudaStreamWaitEvent(sC, evM[it], 0);
        small_stats2<<<1, 256, 0, sC>>>(Wk, Wq, bk, bq);
        cudaEventRecord(evS[it], sC);

        // ---- stream A: W2 planes ---------------------------------------------
        small_mm<<<dim3(4, 4), 256>>>(Wq);

        // ---- attn: Rn = ((R@W2 + c2)*s + vsum) / (s*denp + N) ----------------
        cudaStreamWaitEvent(0, evD[it], 0);
        cudaStreamWaitEvent(0, evS[it], 0);
        mma_gemm<1><<<dim3(4, mtiles, 1), 256, 2 * STAGE_BYTES>>>(
            pRh, pRl, 256, pW2Th, pW2Tl, 256, N, 256, 256, pC2, pRn, 0, (float)N);

        // ---- join gather, blend + LN ----------------------------------------
        cudaStreamWaitEvent(0, evG[it], 0);
        blend_ln<<<(N + 31) / 32, 256>>>(alpha, gamma, beta, Wr, br, wgt,
                                         it + 1, out, N, it < 2 ? 1 : 0);
        if (it < 2) cudaEventRecord(evL[it], 0);
    }
}